// round 15
// baseline (speedup 1.0000x reference)
#include <cuda_runtime.h>
#include <cuda_fp16.h>
#include <cstdint>

#define BATCH 4096
#define T 64
#define D 128
#define TD 8192
#define SPLITK 8

// Scratch (__device__ globals per allocation-free rule)
__device__ __half g_w1h[(size_t)D * TD];             // W1 fp16, [n][k] (2MB)
__device__ __half g_w2h[(size_t)TD * D];             // W2 fp16, [n][k] (2MB)
__device__ __half g_hp[(size_t)SPLITK * BATCH * D];  // gemm1 partials fp16 (8MB)
__device__ __half g_ht[(size_t)BATCH * D];           // relu(h+b1) fp16 (1MB)
__device__ __half g_ypart[(size_t)BATCH * TD];       // X + X_dot fp16 (64MB)

// ---------------- helpers ----------------
__device__ __forceinline__ unsigned pack2(float lo, float hi) {
    unsigned r;
    asm("cvt.rn.f16x2.f32 %0, %1, %2;" : "=r"(r) : "f"(hi), "f"(lo));
    return r;
}
__device__ __forceinline__ uint4 pack8(float4 v0, float4 v1) {
    uint4 u;
    u.x = pack2(v0.x, v0.y); u.y = pack2(v0.z, v0.w);
    u.z = pack2(v1.x, v1.y); u.w = pack2(v1.z, v1.w);
    return u;
}
__device__ __forceinline__ void mma_f16(float* c,
    unsigned a0, unsigned a1, unsigned a2, unsigned a3, unsigned b0, unsigned b1)
{
    asm volatile(
        "mma.sync.aligned.m16n8k16.row.col.f32.f16.f16.f32 "
        "{%0,%1,%2,%3}, {%4,%5,%6,%7}, {%8,%9}, {%0,%1,%2,%3};\n"
        : "+f"(c[0]), "+f"(c[1]), "+f"(c[2]), "+f"(c[3])
        : "r"(a0), "r"(a1), "r"(a2), "r"(a3), "r"(b0), "r"(b1));
}
__device__ __forceinline__ void cp16(__half* smem_dst, const __half* gsrc) {
    unsigned sa = (unsigned)__cvta_generic_to_shared(smem_dst);
    asm volatile("cp.async.cg.shared.global [%0], [%1], 16;\n" :: "r"(sa), "l"(gsrc));
}
__device__ __forceinline__ void ldsm_x4(unsigned& r0, unsigned& r1,
                                        unsigned& r2, unsigned& r3, const __half* p)
{
    unsigned a = (unsigned)__cvta_generic_to_shared(p);
    asm volatile("ldmatrix.sync.aligned.m8n8.x4.shared.b16 {%0,%1,%2,%3}, [%4];"
        : "=r"(r0), "=r"(r1), "=r"(r2), "=r"(r3) : "r"(a));
}
__device__ __forceinline__ void ldsm_x4_t(unsigned& r0, unsigned& r1,
                                          unsigned& r2, unsigned& r3, const __half* p)
{
    unsigned a = (unsigned)__cvta_generic_to_shared(p);
    asm volatile("ldmatrix.sync.aligned.m8n8.x4.trans.shared.b16 {%0,%1,%2,%3}, [%4];"
        : "=r"(r0), "=r"(r1), "=r"(r2), "=r"(r3) : "r"(a));
}
// A-style ldsm lane offset: 16x16 tile at (R, C), row stride S (halves)
#define LDSM_A_OFF(R, C, S)  (((R) + l7 + lb8 * 8) * (S) + (C) + lc16 * 8)
// B-style (non-trans) lane offset: 16 n-rows at N0, k cols at C
#define LDSM_B_OFF(N0, C, S) (((N0) + lc16 * 8 + l7) * (S) + (C) + lb8 * 8)

// ============================================================
// Prep: W1 (1M) and W2 (1M) fp32 -> fp16, layouts already [n][k]
// ============================================================
__global__ void __launch_bounds__(256) prep_w_kernel(
    const float* __restrict__ W1, const float* __restrict__ W2)
{
    size_t o = (size_t)(blockIdx.x * 256 + threadIdx.x) * 8;
    const size_t NW = (size_t)D * TD;
    const float* src = (o < NW) ? (W1 + o) : (W2 + (o - NW));
    __half* dst = (o < NW) ? (g_w1h + o) : (g_w2h + (o - NW));
    float4 v0 = *reinterpret_cast<const float4*>(src);
    float4 v1 = *reinterpret_cast<const float4*>(src + 4);
    *reinterpret_cast<uint4*>(dst) = pack8(v0, v1);
}

// ============================================================
// Kernel 1: split-K GEMM  h_part = X(4096x8192) @ W1^T (fp16 mma + ldmatrix)
// grid (32, 8), 256 thr. M_TILE=128, N=128, K chunk=1024, K_TILE=64.
// ============================================================
__global__ void __launch_bounds__(256, 2) gemm1_kernel(const float* __restrict__ X)
{
    extern __shared__ __half smh[];
    __half* Asm = smh;                 // 2 stages x 9216 halves (128 x 72)
    __half* Bsm = smh + 2 * 9216;

    const int m0 = blockIdx.x * 128;
    const int k0 = blockIdx.y * 1024;
    const int tid = threadIdx.x;
    const int wid = tid >> 5, lane = tid & 31;
    const int l7 = lane & 7, lb8 = (lane >> 3) & 1, lc16 = lane >> 4;
    const int g = lane >> 2, tg = lane & 3;
    const int wm = wid & 3, wn = wid >> 2;     // warp tile 32m x 64n

    int r4[4], o4[4];
#pragma unroll
    for (int i = 0; i < 4; i++) { int q = tid + i * 256; r4[i] = q >> 3; o4[i] = q & 7; }

    float acc[2][8][4];
#pragma unroll
    for (int m = 0; m < 2; m++)
#pragma unroll
        for (int i = 0; i < 8; i++)
#pragma unroll
            for (int j = 0; j < 4; j++) acc[m][i][j] = 0.f;

    float4 av[4][2];

#define G1_LDA(KK)                                                               \
    {                                                                            \
        _Pragma("unroll")                                                        \
        for (int i = 0; i < 4; i++) {                                            \
            const float* p = X + (size_t)(m0 + r4[i]) * TD + (KK) + o4[i] * 8;   \
            av[i][0] = *reinterpret_cast<const float4*>(p);                      \
            av[i][1] = *reinterpret_cast<const float4*>(p + 4);                  \
        }                                                                        \
    }
#define G1_STA(S)                                                                \
    {                                                                            \
        _Pragma("unroll")                                                        \
        for (int i = 0; i < 4; i++)                                              \
            *reinterpret_cast<uint4*>(Asm + (S) * 9216 + r4[i] * 72 + o4[i] * 8) \
                = pack8(av[i][0], av[i][1]);                                     \
    }
#define G1_CPB(S, KK)                                                            \
    {                                                                            \
        _Pragma("unroll")                                                        \
        for (int i = 0; i < 4; i++)                                              \
            cp16(Bsm + (S) * 9216 + r4[i] * 72 + o4[i] * 8,                      \
                 g_w1h + (size_t)r4[i] * TD + (KK) + o4[i] * 8);                 \
        asm volatile("cp.async.commit_group;\n");                                \
    }

    int kk = k0;
    G1_LDA(kk);
    G1_CPB(0, kk);
    G1_STA(0);
    asm volatile("cp.async.wait_group 0;\n");
    __syncthreads();

    for (int kt = 0; kt < 16; kt++) {
        const int cur = kt & 1, nxt = cur ^ 1;
        if (kt < 15) {
            G1_CPB(nxt, kk + 64);
            G1_LDA(kk + 64);
        }
        const __half* A = Asm + cur * 9216;
        const __half* B = Bsm + cur * 9216;
#pragma unroll
        for (int ks = 0; ks < 4; ks++) {
            unsigned a[2][4];
#pragma unroll
            for (int ms = 0; ms < 2; ms++)
                ldsm_x4(a[ms][0], a[ms][1], a[ms][2], a[ms][3],
                        A + LDSM_A_OFF(wm * 32 + ms * 16, ks * 16, 72));
#pragma unroll
            for (int ntp = 0; ntp < 4; ntp++) {
                unsigned b00, b01, b10, b11;
                ldsm_x4(b00, b01, b10, b11,
                        B + LDSM_B_OFF(wn * 64 + ntp * 16, ks * 16, 72));
#pragma unroll
                for (int ms = 0; ms < 2; ms++) {
                    mma_f16(acc[ms][ntp * 2],     a[ms][0], a[ms][1], a[ms][2], a[ms][3], b00, b01);
                    mma_f16(acc[ms][ntp * 2 + 1], a[ms][0], a[ms][1], a[ms][2], a[ms][3], b10, b11);
                }
            }
        }
        if (kt < 15) {
            G1_STA(nxt);
            asm volatile("cp.async.wait_group 0;\n");
        }
        __syncthreads();
        kk += 64;
    }

    // stage output in smem (stride 136), then coalesced uint4 stores
    __half* Sg = smh;   // 128 x 136 halves
#pragma unroll
    for (int ms = 0; ms < 2; ms++)
#pragma unroll
        for (int nt = 0; nt < 8; nt++) {
            int row = wm * 32 + ms * 16 + g;
            int col = wn * 64 + nt * 8 + 2 * tg;
            *reinterpret_cast<unsigned*>(Sg + row * 136 + col) =
                pack2(acc[ms][nt][0], acc[ms][nt][1]);
            *reinterpret_cast<unsigned*>(Sg + (row + 8) * 136 + col) =
                pack2(acc[ms][nt][2], acc[ms][nt][3]);
        }
    __syncthreads();
    __half* outp = g_hp + (size_t)blockIdx.y * BATCH * D;
#pragma unroll
    for (int i = 0; i < 8; i++) {
        int q = tid + i * 256;
        int r = q >> 4, o = q & 15;
        *reinterpret_cast<uint4*>(outp + (size_t)(m0 + r) * D + o * 8) =
            *reinterpret_cast<uint4*>(Sg + r * 136 + o * 8);
    }
}

// ============================================================
// Kernel 1b: g_ht = fp16( relu( sum_p g_hp[p] + b1 ) )
// ============================================================
__global__ void __launch_bounds__(256) reduce_relu_kernel(const float* __restrict__ b1)
{
    const int idx = blockIdx.x * 256 + threadIdx.x;   // 131072 chunks
    const size_t base = (size_t)idx * 4;
    const int col = (idx & 31) * 4;
    float4 s = *reinterpret_cast<const float4*>(b1 + col);
#pragma unroll
    for (int p = 0; p < SPLITK; p++) {
        uint2 u = *reinterpret_cast<const uint2*>(g_hp + (size_t)p * BATCH * D + base);
        float2 f0 = __half22float2(*reinterpret_cast<__half2*>(&u.x));
        float2 f1 = __half22float2(*reinterpret_cast<__half2*>(&u.y));
        s.x += f0.x; s.y += f0.y; s.z += f1.x; s.w += f1.y;
    }
    s.x = fmaxf(s.x, 0.f); s.y = fmaxf(s.y, 0.f);
    s.z = fmaxf(s.z, 0.f); s.w = fmaxf(s.w, 0.f);
    uint2 o;
    o.x = pack2(s.x, s.y);
    o.y = pack2(s.z, s.w);
    *reinterpret_cast<uint2*>(g_ht + base) = o;
}

// ============================================================
// Kernel 2 (v2): attention, 2 batches/CTA, 4 warps/batch, warp owns FULL rows.
// - quad-only softmax (no cross-warp exchange)
// - PV A-fragments taken DIRECTLY from QK accumulator registers
//   (no probs smem round trip)
// - PV in two n-halves to cap acc registers at 32
// smem: Xn[2] 64x136 + Sg[2] 64x136 = 69,632 B -> 3 CTAs/SM. 2 syncs total.
// ============================================================
__global__ void __launch_bounds__(256, 3) attn_kernel(const float* __restrict__ X)
{
    extern __shared__ __half smh[];
    __half* XnBase = smh;              // 2 x (64 x 136)
    __half* SgBase = smh + 17408;      // 2 x (64 x 136)

    const int tid = threadIdx.x, wid = tid >> 5, lane = tid & 31;
    const int g = lane >> 2, tg = lane & 3;
    const int l7 = lane & 7, lb8 = (lane >> 3) & 1, lc16 = lane >> 4;
    const int wg = wid >> 2;           // batch slot within CTA (0/1)
    const int wm = wid & 3;            // rows wm*16 .. +15

    const int b0 = blockIdx.x * 2;

    // fill both Xn tiles (fp32 -> fp16), fully coalesced
#pragma unroll
    for (int i = 0; i < 8; i++) {
        int q = tid + i * 256;         // 2048 octets
        int r = q >> 4, o = q & 15;    // r: 0..127
        int bb = r >> 6, row = r & 63;
        const float* p = X + (size_t)(b0 + bb) * TD + row * D + o * 8;
        float4 v0 = *reinterpret_cast<const float4*>(p);
        float4 v1 = *reinterpret_cast<const float4*>(p + 4);
        *reinterpret_cast<uint4*>(XnBase + bb * 8704 + row * 136 + o * 8) = pack8(v0, v1);
    }
    __syncthreads();

    const __half* Xn = XnBase + wg * 8704;
    __half* Sg = SgBase + wg * 8704;

    // QK: warp tile 16m x 64n (all tokens) — scores stay in registers
    float sc[8][4];
#pragma unroll
    for (int i = 0; i < 8; i++)
#pragma unroll
        for (int j = 0; j < 4; j++) sc[i][j] = 0.f;
#pragma unroll
    for (int ks = 0; ks < 8; ks++) {
        unsigned a0, a1, a2, a3;
        ldsm_x4(a0, a1, a2, a3, Xn + LDSM_A_OFF(wm * 16, ks * 16, 136));
#pragma unroll
        for (int nb = 0; nb < 4; nb++) {
            unsigned b00, b01, b10, b11;
            ldsm_x4(b00, b01, b10, b11,
                    Xn + LDSM_B_OFF(nb * 16, ks * 16, 136));
            mma_f16(sc[nb * 2],     a0, a1, a2, a3, b00, b01);
            mma_f16(sc[nb * 2 + 1], a0, a1, a2, a3, b10, b11);
        }
    }

    // ---- register softmax (quad shuffles only; warp owns full rows) ----
    const float scale = 0.0883883476483184f;   // 128^-0.5
    float m0 = -1e30f, m1 = -1e30f;
#pragma unroll
    for (int nt = 0; nt < 8; nt++) {
        sc[nt][0] *= scale; sc[nt][1] *= scale;
        sc[nt][2] *= scale; sc[nt][3] *= scale;
        m0 = fmaxf(m0, fmaxf(sc[nt][0], sc[nt][1]));
        m1 = fmaxf(m1, fmaxf(sc[nt][2], sc[nt][3]));
    }
    m0 = fmaxf(m0, __shfl_xor_sync(~0u, m0, 1));
    m0 = fmaxf(m0, __shfl_xor_sync(~0u, m0, 2));
    m1 = fmaxf(m1, __shfl_xor_sync(~0u, m1, 1));
    m1 = fmaxf(m1, __shfl_xor_sync(~0u, m1, 2));
    float s0 = 0.f, s1 = 0.f;
#pragma unroll
    for (int nt = 0; nt < 8; nt++) {
        sc[nt][0] = __expf(sc[nt][0] - m0); s0 += sc[nt][0];
        sc[nt][1] = __expf(sc[nt][1] - m0); s0 += sc[nt][1];
        sc[nt][2] = __expf(sc[nt][2] - m1); s1 += sc[nt][2];
        sc[nt][3] = __expf(sc[nt][3] - m1); s1 += sc[nt][3];
    }
    s0 += __shfl_xor_sync(~0u, s0, 1); s0 += __shfl_xor_sync(~0u, s0, 2);
    s1 += __shfl_xor_sync(~0u, s1, 1); s1 += __shfl_xor_sync(~0u, s1, 2);
    const float inv0 = 1.f / s0, inv1 = 1.f / s1;

    // pack fp16 probs straight into PV A-fragment registers
    unsigned prA[8], prB[8];
#pragma unroll
    for (int nt = 0; nt < 8; nt++) {
        prA[nt] = pack2(sc[nt][0] * inv0, sc[nt][1] * inv0);   // row g
        prB[nt] = pack2(sc[nt][2] * inv1, sc[nt][3] * inv1);   // row g+8
    }

    // PV: warp tile 16m x 128n, computed in two 64-wide halves.
    // A-frags come from registers; B via ldmatrix.trans on Xn.
#pragma unroll
    for (int nh = 0; nh < 2; nh++) {
        float acc[8][4];
#pragma unroll
        for (int i = 0; i < 8; i++)
#pragma unroll
            for (int j = 0; j < 4; j++) acc[i][j] = 0.f;
#pragma unroll
        for (int ks = 0; ks < 4; ks++) {
            unsigned a0 = prA[2 * ks],     a1 = prB[2 * ks];
            unsigned a2 = prA[2 * ks + 1], a3 = prB[2 * ks + 1];
#pragma unroll
            for (int ntp = 0; ntp < 4; ntp++) {
                unsigned b00, b01, b10, b11;
                ldsm_x4_t(b00, b01, b10, b11,
                          Xn + LDSM_A_OFF(ks * 16, nh * 64 + ntp * 16, 136));
                mma_f16(acc[ntp * 2],     a0, a1, a2, a3, b00, b01);
                mma_f16(acc[ntp * 2 + 1], a0, a1, a2, a3, b10, b11);
            }
        }
        // stage this half (each warp writes only its own rows — no sync needed)
#pragma unroll
        for (int nt = 0; nt < 8; nt++) {
            int col = nh * 64 + nt * 8 + 2 * tg;
            int row = wm * 16 + g;
            *reinterpret_cast<unsigned*>(Sg + row * 136 + col) =
                pack2(acc[nt][0], acc[nt][1]);
            *reinterpret_cast<unsigned*>(Sg + (row + 8) * 136 + col) =
                pack2(acc[nt][2], acc[nt][3]);
        }
    }
    __syncthreads();

    // coalesced ypart = stage + X (fp16 adds), uint4 stores, both batches
#pragma unroll
    for (int i = 0; i < 8; i++) {
        int q = tid + i * 256;
        int r = q >> 4, o = q & 15;
        int bb = r >> 6, row = r & 63;
        uint4 s = *reinterpret_cast<uint4*>(SgBase + bb * 8704 + row * 136 + o * 8);
        uint4 x = *reinterpret_cast<uint4*>(XnBase + bb * 8704 + row * 136 + o * 8);
        uint4 w;
        reinterpret_cast<__half2*>(&w)[0] =
            __hadd2(reinterpret_cast<__half2*>(&s)[0], reinterpret_cast<__half2*>(&x)[0]);
        reinterpret_cast<__half2*>(&w)[1] =
            __hadd2(reinterpret_cast<__half2*>(&s)[1], reinterpret_cast<__half2*>(&x)[1]);
        reinterpret_cast<__half2*>(&w)[2] =
            __hadd2(reinterpret_cast<__half2*>(&s)[2], reinterpret_cast<__half2*>(&x)[2]);
        reinterpret_cast<__half2*>(&w)[3] =
            __hadd2(reinterpret_cast<__half2*>(&s)[3], reinterpret_cast<__half2*>(&x)[3]);
        *reinterpret_cast<uint4*>(g_ypart + (size_t)(b0 + bb) * TD + row * D + o * 8) = w;
    }
}

// ============================================================
// Kernel 3: out = LN( ypart + b2 + g_ht @ W2^T ) * gamma + beta
// grid (32, 64), 256 thr. M_TILE=128, N=128, K=128. 2 CTAs/SM.
// Yp smem prefetch (cp.async group 1) + register LayerNorm.
// ============================================================
__global__ void __launch_bounds__(256, 2) gemm2_ln_kernel(
    const float* __restrict__ b2, const float* __restrict__ gamma,
    const float* __restrict__ beta, float* __restrict__ out)
{
    extern __shared__ __half smh[];
    __half* As = smh;                     // 128 x 136
    __half* Bs = smh + 17408;             // 128 x 136
    __half* Yp = smh + 34816;             // 128 x 136
    __shared__ float2 sstat[4][2][32];    // (wm, wn, local row) partial (sum, sumsq)

    const int m0 = blockIdx.x * 128;
    const int t  = blockIdx.y;
    const int tid = threadIdx.x, wid = tid >> 5, lane = tid & 31;
    const int g = lane >> 2, tg = lane & 3;
    const int l7 = lane & 7, lb8 = (lane >> 3) & 1, lc16 = lane >> 4;
    const int wm = wid & 3, wn = wid >> 2;      // warp tile 32m x 64n

    // group 0: A (relu(h)) + B (W2 token tile)
#pragma unroll
    for (int i = 0; i < 8; i++) {
        int q = tid + i * 256;
        int r = q >> 4, o = q & 15;
        cp16(As + r * 136 + o * 8, g_ht + (size_t)(m0 + r) * D + o * 8);
        cp16(Bs + r * 136 + o * 8, g_w2h + (size_t)(t * D + r) * D + o * 8);
    }
    asm volatile("cp.async.commit_group;\n");
    // group 1: ypart tile (consumed only in epilogue — overlaps mainloop)
#pragma unroll
    for (int i = 0; i < 8; i++) {
        int q = tid + i * 256;
        int r = q >> 4, o = q & 15;
        cp16(Yp + r * 136 + o * 8, g_ypart + (size_t)(m0 + r) * TD + t * D + o * 8);
    }
    asm volatile("cp.async.commit_group;\n");
    asm volatile("cp.async.wait_group 1;\n");   // A+B ready; Yp may be in flight
    __syncthreads();

    float acc[2][8][4];
#pragma unroll
    for (int m = 0; m < 2; m++)
#pragma unroll
        for (int i = 0; i < 8; i++)
#pragma unroll
            for (int j = 0; j < 4; j++) acc[m][i][j] = 0.f;

#pragma unroll
    for (int ks = 0; ks < 8; ks++) {
        unsigned a[2][4];
#pragma unroll
        for (int ms = 0; ms < 2; ms++)
            ldsm_x4(a[ms][0], a[ms][1], a[ms][2], a[ms][3],
                    As + LDSM_A_OFF(wm * 32 + ms * 16, ks * 16, 136));
#pragma unroll
        for (int ntp = 0; ntp < 4; ntp++) {
            unsigned b00, b01, b10, b11;
            ldsm_x4(b00, b01, b10, b11,
                    Bs + LDSM_B_OFF(wn * 64 + ntp * 16, ks * 16, 136));
#pragma unroll
            for (int ms = 0; ms < 2; ms++) {
                mma_f16(acc[ms][ntp * 2],     a[ms][0], a[ms][1], a[ms][2], a[ms][3], b00, b01);
                mma_f16(acc[ms][ntp * 2 + 1], a[ms][0], a[ms][1], a[ms][2], a[ms][3], b10, b11);
            }
        }
    }
    asm volatile("cp.async.wait_group 0;\n");   // Yp landed
    __syncthreads();                            // Yp visible to all threads

    // ---- fold in ypart + b2 (registers) and accumulate row stats ----
    float rs_sum[2][2] = {{0.f, 0.f}, {0.f, 0.f}};   // [ms][row-half]
    float rs_sq [2][2] = {{0.f, 0.f}, {0.f, 0.f}};
#pragma unroll
    for (int ms = 0; ms < 2; ms++) {
        int row = wm * 32 + ms * 16 + g;
#pragma unroll
        for (int nt = 0; nt < 8; nt++) {
            int col = wn * 64 + nt * 8 + 2 * tg;
            float2 y0 = __half22float2(
                *reinterpret_cast<const __half2*>(Yp + row * 136 + col));
            float2 y1 = __half22float2(
                *reinterpret_cast<const __half2*>(Yp + (row + 8) * 136 + col));
            float2 bb = *reinterpret_cast<const float2*>(b2 + t * D + col);
            float v00 = acc[ms][nt][0] + y0.x + bb.x;
            float v01 = acc[ms][nt][1] + y0.y + bb.y;
            float v10 = acc[ms][nt][2] + y1.x + bb.x;
            float v11 = acc[ms][nt][3] + y1.y + bb.y;
            acc[ms][nt][0] = v00; acc[ms][nt][1] = v01;
            acc[ms][nt][2] = v10; acc[ms][nt][3] = v11;
            rs_sum[ms][0] += v00 + v01;
            rs_sq [ms][0] += v00 * v00 + v01 * v01;
            rs_sum[ms][1] += v10 + v11;
            rs_sq [ms][1] += v10 * v10 + v11 * v11;
        }
    }
#pragma unroll
    for (int ms = 0; ms < 2; ms++)
#pragma unroll
        for (int h = 0; h < 2; h++) {
            rs_sum[ms][h] += __shfl_xor_sync(~0u, rs_sum[ms][h], 1);
            rs_sum[ms][h] += __shfl_xor_sync(~0u, rs_sum[ms][h], 2);
            rs_sq [ms][h] += __shfl_xor_sync(~0u, rs_sq [ms][h], 1);
            rs_sq [ms][h] += __shfl_xor_sync(~0u, rs_sq [ms][h], 2);
        }
    if (tg == 0) {
#pragma unroll
        for (int ms = 0; ms < 2; ms++) {
            sstat[wm][wn][ms * 16 + g]     = make_float2(rs_sum[ms][0], rs_sq[ms][0]);
            sstat[wm][wn][ms * 16 + 8 + g] = make_float2(rs_sum[ms][1], rs_sq[ms][1]);
        }
    }
    __syncthreads();

    float mu[2][2], rsg[2][2];
#pragma unroll
    for (int ms = 0; ms < 2; ms++)
#pragma unroll
        for (int h = 0; h < 2; h++) {
            float2 other = sstat[wm][wn ^ 1][ms * 16 + h * 8 + g];
            float S = rs_sum[ms][h] + other.x;
            float Q = rs_sq [ms][h] + other.y;
            float m = S * (1.f / 128.f);
            float var = Q * (1.f / 128.f) - m * m;
            mu[ms][h] = m;
            rsg[ms][h] = rsqrtf(var + 1e-5f);
        }

#pragma unroll
    for (int ms = 0; ms < 2; ms++) {
        int row = m0 + wm * 32 + ms * 16 + g;
#pragma unroll
        for (int nt = 0; nt < 8; nt++) {
            int col = wn * 64 + nt * 8 + 2 * tg;
            float2 gm = *reinterpret_cast<const float2*>(gamma + col);
            float2 bt = *reinterpret_cast<const float2*>(beta + col);
            float2 o0, o1;
            o0.x = (acc[ms][nt][0] - mu[ms][0]) * rsg[ms][0] * gm.x + bt.x;
            o0.y = (acc[ms][nt][1] - mu[ms][0]) * rsg[ms][0] * gm.y + bt.y;
            o1.x = (acc[ms][nt][2] - mu[ms][1]) * rsg[ms][1] * gm.x + bt.x;
            o1.y = (acc[ms][nt][3] - mu[ms][1]) * rsg[ms][1] * gm.y + bt.y;
            *reinterpret_cast<float2*>(out + (size_t)row * TD + t * D + col) = o0;
            *reinterpret_cast<float2*>(out + (size_t)(row + 8) * TD + t * D + col) = o1;
        }
    }
}

// ============================================================
// Launcher: round-12 proven fork/join (single extra stream, 2 events).
// ============================================================
extern "C" void kernel_launch(void* const* d_in, const int* in_sizes, int n_in,
                              void* d_out, int out_size)
{
    const float* X     = (const float*)d_in[0];
    const float* W1    = (const float*)d_in[1];
    const float* b1    = (const float*)d_in[2];
    const float* W2    = (const float*)d_in[3];
    const float* b2    = (const float*)d_in[4];
    const float* gamma = (const float*)d_in[5];
    const float* beta  = (const float*)d_in[6];
    float* out = (float*)d_out;

    const int smem_g1   = 4 * 9216 * 2;                 // 73,728 B
    const int smem_attn = 4 * 8704 * 2;                 // 69,632 B
    const int smem_g2   = 3 * 17408 * 2;                // 104,448 B
    cudaFuncSetAttribute(gemm1_kernel,
        cudaFuncAttributeMaxDynamicSharedMemorySize, smem_g1);
    cudaFuncSetAttribute(attn_kernel,
        cudaFuncAttributeMaxDynamicSharedMemorySize, smem_attn);
    cudaFuncSetAttribute(gemm2_ln_kernel,
        cudaFuncAttributeMaxDynamicSharedMemorySize, smem_g2);

    cudaStream_t s2;
    cudaStreamCreateWithFlags(&s2, cudaStreamNonBlocking);
    cudaEvent_t eFork, eJoin;
    cudaEventCreateWithFlags(&eFork, cudaEventDisableTiming);
    cudaEventCreateWithFlags(&eJoin, cudaEventDisableTiming);

    // fork: attn (depends only on X) on s2
    cudaEventRecord(eFork, 0);
    cudaStreamWaitEvent(s2, eFork, 0);
    attn_kernel<<<BATCH / 2, 256, smem_attn, s2>>>(X);
    cudaEventRecord(eJoin, s2);

    // main chain: prep -> gemm1 -> reduce
    prep_w_kernel<<<1024, 256>>>(W1, W2);
    gemm1_kernel<<<dim3(32, SPLITK), 256, smem_g1>>>(X);
    reduce_relu_kernel<<<512, 256>>>(b1);

    // join, then gemm2 (needs ht + ypart)
    cudaStreamWaitEvent(0, eJoin, 0);
    gemm2_ln_kernel<<<dim3(32, 64), 256, smem_g2>>>(b2, gamma, beta, out);
}

// round 16
// speedup vs baseline: 1.1057x; 1.1057x over previous
#include <cuda_runtime.h>
#include <cuda_fp16.h>
#include <cstdint>

#define BATCH 4096
#define T 64
#define D 128
#define TD 8192
#define SPLITK 8

// Scratch (__device__ globals per allocation-free rule)
__device__ __half g_w1h[(size_t)D * TD];             // W1 fp16, [n][k] (2MB)
__device__ __half g_w2h[(size_t)TD * D];             // W2 fp16, [n][k] (2MB)
__device__ __half g_hp[(size_t)SPLITK * BATCH * D];  // gemm1 partials fp16 (8MB)
__device__ __half g_ht[(size_t)BATCH * D];           // relu(h+b1) fp16 (1MB)
__device__ __half g_ypart[(size_t)BATCH * TD];       // X + X_dot fp16 (64MB)

// ---------------- helpers ----------------
__device__ __forceinline__ unsigned pack2(float lo, float hi) {
    unsigned r;
    asm("cvt.rn.f16x2.f32 %0, %1, %2;" : "=r"(r) : "f"(hi), "f"(lo));
    return r;
}
__device__ __forceinline__ uint4 pack8(float4 v0, float4 v1) {
    uint4 u;
    u.x = pack2(v0.x, v0.y); u.y = pack2(v0.z, v0.w);
    u.z = pack2(v1.x, v1.y); u.w = pack2(v1.z, v1.w);
    return u;
}
__device__ __forceinline__ void mma_f16(float* c,
    unsigned a0, unsigned a1, unsigned a2, unsigned a3, unsigned b0, unsigned b1)
{
    asm volatile(
        "mma.sync.aligned.m16n8k16.row.col.f32.f16.f16.f32 "
        "{%0,%1,%2,%3}, {%4,%5,%6,%7}, {%8,%9}, {%0,%1,%2,%3};\n"
        : "+f"(c[0]), "+f"(c[1]), "+f"(c[2]), "+f"(c[3])
        : "r"(a0), "r"(a1), "r"(a2), "r"(a3), "r"(b0), "r"(b1));
}
__device__ __forceinline__ void cp16(__half* smem_dst, const __half* gsrc) {
    unsigned sa = (unsigned)__cvta_generic_to_shared(smem_dst);
    asm volatile("cp.async.cg.shared.global [%0], [%1], 16;\n" :: "r"(sa), "l"(gsrc));
}
__device__ __forceinline__ void ldsm_x4(unsigned& r0, unsigned& r1,
                                        unsigned& r2, unsigned& r3, const __half* p)
{
    unsigned a = (unsigned)__cvta_generic_to_shared(p);
    asm volatile("ldmatrix.sync.aligned.m8n8.x4.shared.b16 {%0,%1,%2,%3}, [%4];"
        : "=r"(r0), "=r"(r1), "=r"(r2), "=r"(r3) : "r"(a));
}
__device__ __forceinline__ void ldsm_x4_t(unsigned& r0, unsigned& r1,
                                          unsigned& r2, unsigned& r3, const __half* p)
{
    unsigned a = (unsigned)__cvta_generic_to_shared(p);
    asm volatile("ldmatrix.sync.aligned.m8n8.x4.trans.shared.b16 {%0,%1,%2,%3}, [%4];"
        : "=r"(r0), "=r"(r1), "=r"(r2), "=r"(r3) : "r"(a));
}
// A-style ldsm lane offset: 16x16 tile at (R, C), row stride S (halves)
#define LDSM_A_OFF(R, C, S)  (((R) + l7 + lb8 * 8) * (S) + (C) + lc16 * 8)
// B-style (non-trans) lane offset: 16 n-rows at N0, k cols at C
#define LDSM_B_OFF(N0, C, S) (((N0) + lc16 * 8 + l7) * (S) + (C) + lb8 * 8)

// ============================================================
// Prep: W1 (1M) and W2 (1M) fp32 -> fp16, layouts already [n][k]
// ============================================================
__global__ void __launch_bounds__(256) prep_w_kernel(
    const float* __restrict__ W1, const float* __restrict__ W2)
{
    size_t o = (size_t)(blockIdx.x * 256 + threadIdx.x) * 8;
    const size_t NW = (size_t)D * TD;
    const float* src = (o < NW) ? (W1 + o) : (W2 + (o - NW));
    __half* dst = (o < NW) ? (g_w1h + o) : (g_w2h + (o - NW));
    float4 v0 = *reinterpret_cast<const float4*>(src);
    float4 v1 = *reinterpret_cast<const float4*>(src + 4);
    *reinterpret_cast<uint4*>(dst) = pack8(v0, v1);
}

// ============================================================
// Kernel 1: split-K GEMM  h_part = X(4096x8192) @ W1^T (fp16 mma + ldmatrix)
// grid (32, 8), 256 thr. M_TILE=128, N=128, K chunk=1024, K_TILE=64.
// ============================================================
__global__ void __launch_bounds__(256, 2) gemm1_kernel(const float* __restrict__ X)
{
    extern __shared__ __half smh[];
    __half* Asm = smh;                 // 2 stages x 9216 halves (128 x 72)
    __half* Bsm = smh + 2 * 9216;

    const int m0 = blockIdx.x * 128;
    const int k0 = blockIdx.y * 1024;
    const int tid = threadIdx.x;
    const int wid = tid >> 5, lane = tid & 31;
    const int l7 = lane & 7, lb8 = (lane >> 3) & 1, lc16 = lane >> 4;
    const int g = lane >> 2, tg = lane & 3;
    const int wm = wid & 3, wn = wid >> 2;     // warp tile 32m x 64n

    int r4[4], o4[4];
#pragma unroll
    for (int i = 0; i < 4; i++) { int q = tid + i * 256; r4[i] = q >> 3; o4[i] = q & 7; }

    float acc[2][8][4];
#pragma unroll
    for (int m = 0; m < 2; m++)
#pragma unroll
        for (int i = 0; i < 8; i++)
#pragma unroll
            for (int j = 0; j < 4; j++) acc[m][i][j] = 0.f;

    float4 av[4][2];

#define G1_LDA(KK)                                                               \
    {                                                                            \
        _Pragma("unroll")                                                        \
        for (int i = 0; i < 4; i++) {                                            \
            const float* p = X + (size_t)(m0 + r4[i]) * TD + (KK) + o4[i] * 8;   \
            av[i][0] = *reinterpret_cast<const float4*>(p);                      \
            av[i][1] = *reinterpret_cast<const float4*>(p + 4);                  \
        }                                                                        \
    }
#define G1_STA(S)                                                                \
    {                                                                            \
        _Pragma("unroll")                                                        \
        for (int i = 0; i < 4; i++)                                              \
            *reinterpret_cast<uint4*>(Asm + (S) * 9216 + r4[i] * 72 + o4[i] * 8) \
                = pack8(av[i][0], av[i][1]);                                     \
    }
#define G1_CPB(S, KK)                                                            \
    {                                                                            \
        _Pragma("unroll")                                                        \
        for (int i = 0; i < 4; i++)                                              \
            cp16(Bsm + (S) * 9216 + r4[i] * 72 + o4[i] * 8,                      \
                 g_w1h + (size_t)r4[i] * TD + (KK) + o4[i] * 8);                 \
        asm volatile("cp.async.commit_group;\n");                                \
    }

    int kk = k0;
    G1_LDA(kk);
    G1_CPB(0, kk);
    G1_STA(0);
    asm volatile("cp.async.wait_group 0;\n");
    __syncthreads();

    for (int kt = 0; kt < 16; kt++) {
        const int cur = kt & 1, nxt = cur ^ 1;
        if (kt < 15) {
            G1_CPB(nxt, kk + 64);
            G1_LDA(kk + 64);
        }
        const __half* A = Asm + cur * 9216;
        const __half* B = Bsm + cur * 9216;
#pragma unroll
        for (int ks = 0; ks < 4; ks++) {
            unsigned a[2][4];
#pragma unroll
            for (int ms = 0; ms < 2; ms++)
                ldsm_x4(a[ms][0], a[ms][1], a[ms][2], a[ms][3],
                        A + LDSM_A_OFF(wm * 32 + ms * 16, ks * 16, 72));
#pragma unroll
            for (int ntp = 0; ntp < 4; ntp++) {
                unsigned b00, b01, b10, b11;
                ldsm_x4(b00, b01, b10, b11,
                        B + LDSM_B_OFF(wn * 64 + ntp * 16, ks * 16, 72));
#pragma unroll
                for (int ms = 0; ms < 2; ms++) {
                    mma_f16(acc[ms][ntp * 2],     a[ms][0], a[ms][1], a[ms][2], a[ms][3], b00, b01);
                    mma_f16(acc[ms][ntp * 2 + 1], a[ms][0], a[ms][1], a[ms][2], a[ms][3], b10, b11);
                }
            }
        }
        if (kt < 15) {
            G1_STA(nxt);
            asm volatile("cp.async.wait_group 0;\n");
        }
        __syncthreads();
        kk += 64;
    }

    // stage output in smem (stride 136), then coalesced uint4 stores
    __half* Sg = smh;   // 128 x 136 halves
#pragma unroll
    for (int ms = 0; ms < 2; ms++)
#pragma unroll
        for (int nt = 0; nt < 8; nt++) {
            int row = wm * 32 + ms * 16 + g;
            int col = wn * 64 + nt * 8 + 2 * tg;
            *reinterpret_cast<unsigned*>(Sg + row * 136 + col) =
                pack2(acc[ms][nt][0], acc[ms][nt][1]);
            *reinterpret_cast<unsigned*>(Sg + (row + 8) * 136 + col) =
                pack2(acc[ms][nt][2], acc[ms][nt][3]);
        }
    __syncthreads();
    __half* outp = g_hp + (size_t)blockIdx.y * BATCH * D;
#pragma unroll
    for (int i = 0; i < 8; i++) {
        int q = tid + i * 256;
        int r = q >> 4, o = q & 15;
        *reinterpret_cast<uint4*>(outp + (size_t)(m0 + r) * D + o * 8) =
            *reinterpret_cast<uint4*>(Sg + r * 136 + o * 8);
    }
}

// ============================================================
// Kernel 1b: g_ht = fp16( relu( sum_p g_hp[p] + b1 ) )
// ============================================================
__global__ void __launch_bounds__(256) reduce_relu_kernel(const float* __restrict__ b1)
{
    const int idx = blockIdx.x * 256 + threadIdx.x;   // 131072 chunks
    const size_t base = (size_t)idx * 4;
    const int col = (idx & 31) * 4;
    float4 s = *reinterpret_cast<const float4*>(b1 + col);
#pragma unroll
    for (int p = 0; p < SPLITK; p++) {
        uint2 u = *reinterpret_cast<const uint2*>(g_hp + (size_t)p * BATCH * D + base);
        float2 f0 = __half22float2(*reinterpret_cast<__half2*>(&u.x));
        float2 f1 = __half22float2(*reinterpret_cast<__half2*>(&u.y));
        s.x += f0.x; s.y += f0.y; s.z += f1.x; s.w += f1.y;
    }
    s.x = fmaxf(s.x, 0.f); s.y = fmaxf(s.y, 0.f);
    s.z = fmaxf(s.z, 0.f); s.w = fmaxf(s.w, 0.f);
    uint2 o;
    o.x = pack2(s.x, s.y);
    o.y = pack2(s.z, s.w);
    *reinterpret_cast<uint2*>(g_ht + base) = o;
}

// ============================================================
// Kernel 2: per-batch attention (round-12 proven form: fp16 mma + ldmatrix
// + register softmax, occ 4, coalesced staged epilogue)
// ============================================================
__global__ void __launch_bounds__(256, 4) attn_kernel(const float* __restrict__ X)
{
    extern __shared__ __half smh[];
    __half* Xn = smh;                  // 64 x 136
    __half* Ps = smh + 8704;           // 64 x 136 (fp16 probs; stage alias later)
    __shared__ float2 sst[4][2][16];   // (wm, wn, row-in-warp) partial (max, sum)

    const int b = blockIdx.x;
    const float* Xb = X + (size_t)b * TD;
    const int tid = threadIdx.x, wid = tid >> 5, lane = tid & 31;
    const int g = lane >> 2, tg = lane & 3;
    const int l7 = lane & 7, lb8 = (lane >> 3) & 1, lc16 = lane >> 4;
    const int wm = wid & 3, wn = wid >> 2;

    // fill Xn (convert fp32 -> fp16)
#pragma unroll
    for (int i = 0; i < 4; i++) {
        int q = tid + i * 256;
        int r = q >> 4, o = q & 15;
        const float* p = Xb + r * D + o * 8;
        float4 v0 = *reinterpret_cast<const float4*>(p);
        float4 v1 = *reinterpret_cast<const float4*>(p + 4);
        *reinterpret_cast<uint4*>(Xn + r * 136 + o * 8) = pack8(v0, v1);
    }
    __syncthreads();

    // QK: scores = X X^T * scale; warp tile 16m x 32n — kept in registers
    float sc[4][4];
#pragma unroll
    for (int i = 0; i < 4; i++)
#pragma unroll
        for (int j = 0; j < 4; j++) sc[i][j] = 0.f;
#pragma unroll
    for (int ks = 0; ks < 8; ks++) {
        unsigned a0, a1, a2, a3;
        ldsm_x4(a0, a1, a2, a3, Xn + LDSM_A_OFF(wm * 16, ks * 16, 136));
#pragma unroll
        for (int ntp = 0; ntp < 2; ntp++) {
            unsigned b00, b01, b10, b11;
            ldsm_x4(b00, b01, b10, b11,
                    Xn + LDSM_B_OFF(wn * 32 + ntp * 16, ks * 16, 136));
            mma_f16(sc[ntp * 2],     a0, a1, a2, a3, b00, b01);
            mma_f16(sc[ntp * 2 + 1], a0, a1, a2, a3, b10, b11);
        }
    }

    // ---- register softmax ----
    const float scale = 0.0883883476483184f;   // 128^-0.5
    float m0 = -1e30f, m1 = -1e30f;
#pragma unroll
    for (int nt = 0; nt < 4; nt++) {
        sc[nt][0] *= scale; sc[nt][1] *= scale;
        sc[nt][2] *= scale; sc[nt][3] *= scale;
        m0 = fmaxf(m0, fmaxf(sc[nt][0], sc[nt][1]));
        m1 = fmaxf(m1, fmaxf(sc[nt][2], sc[nt][3]));
    }
    m0 = fmaxf(m0, __shfl_xor_sync(~0u, m0, 1));
    m0 = fmaxf(m0, __shfl_xor_sync(~0u, m0, 2));
    m1 = fmaxf(m1, __shfl_xor_sync(~0u, m1, 1));
    m1 = fmaxf(m1, __shfl_xor_sync(~0u, m1, 2));
    float s0 = 0.f, s1 = 0.f;
#pragma unroll
    for (int nt = 0; nt < 4; nt++) {
        sc[nt][0] = __expf(sc[nt][0] - m0); s0 += sc[nt][0];
        sc[nt][1] = __expf(sc[nt][1] - m0); s0 += sc[nt][1];
        sc[nt][2] = __expf(sc[nt][2] - m1); s1 += sc[nt][2];
        sc[nt][3] = __expf(sc[nt][3] - m1); s1 += sc[nt][3];
    }
    s0 += __shfl_xor_sync(~0u, s0, 1); s0 += __shfl_xor_sync(~0u, s0, 2);
    s1 += __shfl_xor_sync(~0u, s1, 1); s1 += __shfl_xor_sync(~0u, s1, 2);
    if (tg == 0) {
        sst[wm][wn][g]     = make_float2(m0, s0);
        sst[wm][wn][8 + g] = make_float2(m1, s1);
    }
    __syncthreads();
    float2 q0 = sst[wm][wn ^ 1][g];
    float2 q1 = sst[wm][wn ^ 1][8 + g];
    float M0 = fmaxf(m0, q0.x);
    float S0 = s0 * __expf(m0 - M0) + q0.y * __expf(q0.x - M0);
    float c0 = __expf(m0 - M0) / S0;
    float M1 = fmaxf(m1, q1.x);
    float S1 = s1 * __expf(m1 - M1) + q1.y * __expf(q1.x - M1);
    float c1 = __expf(m1 - M1) / S1;
#pragma unroll
    for (int nt = 0; nt < 4; nt++) {
        int col = wn * 32 + nt * 8 + 2 * tg;
        int row = wm * 16 + g;
        *reinterpret_cast<unsigned*>(Ps + row * 136 + col) =
            pack2(sc[nt][0] * c0, sc[nt][1] * c0);
        *reinterpret_cast<unsigned*>(Ps + (row + 8) * 136 + col) =
            pack2(sc[nt][2] * c1, sc[nt][3] * c1);
    }
    __syncthreads();

    // PV: X_dot = attn @ X; warp tile 16m x 64n, K=64 tokens.
    float acc[8][4];
#pragma unroll
    for (int i = 0; i < 8; i++)
#pragma unroll
        for (int j = 0; j < 4; j++) acc[i][j] = 0.f;
#pragma unroll
    for (int ks = 0; ks < 4; ks++) {
        unsigned a0, a1, a2, a3;
        ldsm_x4(a0, a1, a2, a3, Ps + LDSM_A_OFF(wm * 16, ks * 16, 136));
#pragma unroll
        for (int ntp = 0; ntp < 4; ntp++) {
            unsigned b00, b01, b10, b11;
            ldsm_x4_t(b00, b01, b10, b11,
                      Xn + LDSM_A_OFF(ks * 16, wn * 64 + ntp * 16, 136));
            mma_f16(acc[ntp * 2],     a0, a1, a2, a3, b00, b01);
            mma_f16(acc[ntp * 2 + 1], a0, a1, a2, a3, b10, b11);
        }
    }
    __syncthreads();   // all PV reads of Ps done — safe to overwrite as stage

    // stage PV result (fp16) into Ps region (stride 136)
    __half* Sg = Ps;
#pragma unroll
    for (int nt = 0; nt < 8; nt++) {
        int col = wn * 64 + nt * 8 + 2 * tg;
        int row = wm * 16 + g;
        *reinterpret_cast<unsigned*>(Sg + row * 136 + col) =
            pack2(acc[nt][0], acc[nt][1]);
        *reinterpret_cast<unsigned*>(Sg + (row + 8) * 136 + col) =
            pack2(acc[nt][2], acc[nt][3]);
    }
    __syncthreads();

    // coalesced ypart = stage + X (fp16 adds), uint4 stores (default policy:
    // ypart WANTS L2 residency — gemm2 reads it next)
    __half* yp = g_ypart + (size_t)b * TD;
#pragma unroll
    for (int i = 0; i < 4; i++) {
        int q = tid + i * 256;
        int r = q >> 4, o = q & 15;
        uint4 s = *reinterpret_cast<uint4*>(Sg + r * 136 + o * 8);
        uint4 x = *reinterpret_cast<uint4*>(Xn + r * 136 + o * 8);
        uint4 w;
        reinterpret_cast<__half2*>(&w)[0] =
            __hadd2(reinterpret_cast<__half2*>(&s)[0], reinterpret_cast<__half2*>(&x)[0]);
        reinterpret_cast<__half2*>(&w)[1] =
            __hadd2(reinterpret_cast<__half2*>(&s)[1], reinterpret_cast<__half2*>(&x)[1]);
        reinterpret_cast<__half2*>(&w)[2] =
            __hadd2(reinterpret_cast<__half2*>(&s)[2], reinterpret_cast<__half2*>(&x)[2]);
        reinterpret_cast<__half2*>(&w)[3] =
            __hadd2(reinterpret_cast<__half2*>(&s)[3], reinterpret_cast<__half2*>(&x)[3]);
        *reinterpret_cast<uint4*>(yp + r * D + o * 8) = w;
    }
}

// ============================================================
// Kernel 3: out = LN( ypart + b2 + g_ht @ W2^T ) * gamma + beta
// grid (32, 64), 256 thr. M_TILE=128, N=128, K=128. 2 CTAs/SM.
// Yp smem prefetch (cp.async group 1) + register LayerNorm.
// out stores use __stcs (streaming hint — written once, never re-read)
// to keep L2 free for ypart reads.
// ============================================================
__global__ void __launch_bounds__(256, 2) gemm2_ln_kernel(
    const float* __restrict__ b2, const float* __restrict__ gamma,
    const float* __restrict__ beta, float* __restrict__ out)
{
    extern __shared__ __half smh[];
    __half* As = smh;                     // 128 x 136
    __half* Bs = smh + 17408;             // 128 x 136
    __half* Yp = smh + 34816;             // 128 x 136
    __shared__ float2 sstat[4][2][32];    // (wm, wn, local row) partial (sum, sumsq)

    const int m0 = blockIdx.x * 128;
    const int t  = blockIdx.y;
    const int tid = threadIdx.x, wid = tid >> 5, lane = tid & 31;
    const int g = lane >> 2, tg = lane & 3;
    const int l7 = lane & 7, lb8 = (lane >> 3) & 1, lc16 = lane >> 4;
    const int wm = wid & 3, wn = wid >> 2;      // warp tile 32m x 64n

    // group 0: A (relu(h)) + B (W2 token tile)
#pragma unroll
    for (int i = 0; i < 8; i++) {
        int q = tid + i * 256;
        int r = q >> 4, o = q & 15;
        cp16(As + r * 136 + o * 8, g_ht + (size_t)(m0 + r) * D + o * 8);
        cp16(Bs + r * 136 + o * 8, g_w2h + (size_t)(t * D + r) * D + o * 8);
    }
    asm volatile("cp.async.commit_group;\n");
    // group 1: ypart tile (consumed only in epilogue — overlaps mainloop)
#pragma unroll
    for (int i = 0; i < 8; i++) {
        int q = tid + i * 256;
        int r = q >> 4, o = q & 15;
        cp16(Yp + r * 136 + o * 8, g_ypart + (size_t)(m0 + r) * TD + t * D + o * 8);
    }
    asm volatile("cp.async.commit_group;\n");
    asm volatile("cp.async.wait_group 1;\n");   // A+B ready; Yp may be in flight
    __syncthreads();

    float acc[2][8][4];
#pragma unroll
    for (int m = 0; m < 2; m++)
#pragma unroll
        for (int i = 0; i < 8; i++)
#pragma unroll
            for (int j = 0; j < 4; j++) acc[m][i][j] = 0.f;

#pragma unroll
    for (int ks = 0; ks < 8; ks++) {
        unsigned a[2][4];
#pragma unroll
        for (int ms = 0; ms < 2; ms++)
            ldsm_x4(a[ms][0], a[ms][1], a[ms][2], a[ms][3],
                    As + LDSM_A_OFF(wm * 32 + ms * 16, ks * 16, 136));
#pragma unroll
        for (int ntp = 0; ntp < 4; ntp++) {
            unsigned b00, b01, b10, b11;
            ldsm_x4(b00, b01, b10, b11,
                    Bs + LDSM_B_OFF(wn * 64 + ntp * 16, ks * 16, 136));
#pragma unroll
            for (int ms = 0; ms < 2; ms++) {
                mma_f16(acc[ms][ntp * 2],     a[ms][0], a[ms][1], a[ms][2], a[ms][3], b00, b01);
                mma_f16(acc[ms][ntp * 2 + 1], a[ms][0], a[ms][1], a[ms][2], a[ms][3], b10, b11);
            }
        }
    }
    asm volatile("cp.async.wait_group 0;\n");   // Yp landed
    __syncthreads();                            // Yp visible to all threads

    // ---- fold in ypart + b2 (registers) and accumulate row stats ----
    float rs_sum[2][2] = {{0.f, 0.f}, {0.f, 0.f}};   // [ms][row-half]
    float rs_sq [2][2] = {{0.f, 0.f}, {0.f, 0.f}};
#pragma unroll
    for (int ms = 0; ms < 2; ms++) {
        int row = wm * 32 + ms * 16 + g;
#pragma unroll
        for (int nt = 0; nt < 8; nt++) {
            int col = wn * 64 + nt * 8 + 2 * tg;
            float2 y0 = __half22float2(
                *reinterpret_cast<const __half2*>(Yp + row * 136 + col));
            float2 y1 = __half22float2(
                *reinterpret_cast<const __half2*>(Yp + (row + 8) * 136 + col));
            float2 bb = *reinterpret_cast<const float2*>(b2 + t * D + col);
            float v00 = acc[ms][nt][0] + y0.x + bb.x;
            float v01 = acc[ms][nt][1] + y0.y + bb.y;
            float v10 = acc[ms][nt][2] + y1.x + bb.x;
            float v11 = acc[ms][nt][3] + y1.y + bb.y;
            acc[ms][nt][0] = v00; acc[ms][nt][1] = v01;
            acc[ms][nt][2] = v10; acc[ms][nt][3] = v11;
            rs_sum[ms][0] += v00 + v01;
            rs_sq [ms][0] += v00 * v00 + v01 * v01;
            rs_sum[ms][1] += v10 + v11;
            rs_sq [ms][1] += v10 * v10 + v11 * v11;
        }
    }
#pragma unroll
    for (int ms = 0; ms < 2; ms++)
#pragma unroll
        for (int h = 0; h < 2; h++) {
            rs_sum[ms][h] += __shfl_xor_sync(~0u, rs_sum[ms][h], 1);
            rs_sum[ms][h] += __shfl_xor_sync(~0u, rs_sum[ms][h], 2);
            rs_sq [ms][h] += __shfl_xor_sync(~0u, rs_sq [ms][h], 1);
            rs_sq [ms][h] += __shfl_xor_sync(~0u, rs_sq [ms][h], 2);
        }
    if (tg == 0) {
#pragma unroll
        for (int ms = 0; ms < 2; ms++) {
            sstat[wm][wn][ms * 16 + g]     = make_float2(rs_sum[ms][0], rs_sq[ms][0]);
            sstat[wm][wn][ms * 16 + 8 + g] = make_float2(rs_sum[ms][1], rs_sq[ms][1]);
        }
    }
    __syncthreads();

    float mu[2][2], rsg[2][2];
#pragma unroll
    for (int ms = 0; ms < 2; ms++)
#pragma unroll
        for (int h = 0; h < 2; h++) {
            float2 other = sstat[wm][wn ^ 1][ms * 16 + h * 8 + g];
            float S = rs_sum[ms][h] + other.x;
            float Q = rs_sq [ms][h] + other.y;
            float m = S * (1.f / 128.f);
            float var = Q * (1.f / 128.f) - m * m;
            mu[ms][h] = m;
            rsg[ms][h] = rsqrtf(var + 1e-5f);
        }

    // write out directly from fragments (float2 streaming stores, 32B-aligned per quad)
#pragma unroll
    for (int ms = 0; ms < 2; ms++) {
        int row = m0 + wm * 32 + ms * 16 + g;
#pragma unroll
        for (int nt = 0; nt < 8; nt++) {
            int col = wn * 64 + nt * 8 + 2 * tg;
            float2 gm = *reinterpret_cast<const float2*>(gamma + col);
            float2 bt = *reinterpret_cast<const float2*>(beta + col);
            float2 o0, o1;
            o0.x = (acc[ms][nt][0] - mu[ms][0]) * rsg[ms][0] * gm.x + bt.x;
            o0.y = (acc[ms][nt][1] - mu[ms][0]) * rsg[ms][0] * gm.y + bt.y;
            o1.x = (acc[ms][nt][2] - mu[ms][1]) * rsg[ms][1] * gm.x + bt.x;
            o1.y = (acc[ms][nt][3] - mu[ms][1]) * rsg[ms][1] * gm.y + bt.y;
            __stcs(reinterpret_cast<float2*>(out + (size_t)row * TD + t * D + col), o0);
            __stcs(reinterpret_cast<float2*>(out + (size_t)(row + 8) * TD + t * D + col), o1);
        }
    }
}

// ============================================================
// Launcher: round-12 proven fork/join (single extra stream, 2 events).
// ============================================================
extern "C" void kernel_launch(void* const* d_in, const int* in_sizes, int n_in,
                              void* d_out, int out_size)
{
    const float* X     = (const float*)d_in[0];
    const float* W1    = (const float*)d_in[1];
    const float* b1    = (const float*)d_in[2];
    const float* W2    = (const float*)d_in[3];
    const float* b2    = (const float*)d_in[4];
    const float* gamma = (const float*)d_in[5];
    const float* beta  = (const float*)d_in[6];
    float* out = (float*)d_out;

    const int smem_g1   = 4 * 9216 * 2;                 // 73,728 B
    const int smem_attn = 2 * 8704 * 2;                 // 34,816 B
    const int smem_g2   = 3 * 17408 * 2;                // 104,448 B
    cudaFuncSetAttribute(gemm1_kernel,
        cudaFuncAttributeMaxDynamicSharedMemorySize, smem_g1);
    cudaFuncSetAttribute(attn_kernel,
        cudaFuncAttributeMaxDynamicSharedMemorySize, smem_attn);
    cudaFuncSetAttribute(gemm2_ln_kernel,
        cudaFuncAttributeMaxDynamicSharedMemorySize, smem_g2);

    cudaStream_t s2;
    cudaStreamCreateWithFlags(&s2, cudaStreamNonBlocking);
    cudaEvent_t eFork, eJoin;
    cudaEventCreateWithFlags(&eFork, cudaEventDisableTiming);
    cudaEventCreateWithFlags(&eJoin, cudaEventDisableTiming);

    // fork: attn (depends only on X) on s2
    cudaEventRecord(eFork, 0);
    cudaStreamWaitEvent(s2, eFork, 0);
    attn_kernel<<<BATCH, 256, smem_attn, s2>>>(X);
    cudaEventRecord(eJoin, s2);

    // main chain: prep -> gemm1 -> reduce
    prep_w_kernel<<<1024, 256>>>(W1, W2);
    gemm1_kernel<<<dim3(32, SPLITK), 256, smem_g1>>>(X);
    reduce_relu_kernel<<<512, 256>>>(b1);

    // join, then gemm2 (needs ht + ypart)
    cudaStreamWaitEvent(0, eJoin, 0);
    gemm2_ln_kernel<<<dim3(32, 64), 256, smem_g2>>>(b2, gamma, beta, out);
}